// round 8
// baseline (speedup 1.0000x reference)
#include <cuda_runtime.h>
#include <cuda_fp16.h>

// Problem constants (match reference)
#define NGRID 512
#define NB    10      // bond types
#define NM    16      // integrals
#define E_EDGES 2000000
#define N_NODES 500000

// Derived output offsets (floats)
#define OUT_OVL_OFF  (E_EDGES * NM)          // 32,000,000
#define OUT_NODE_OFF (2 * E_EDGES * NM)      // 64,000,000

// Grid-pair-interleaved fp16 table.
// Entry (b, i0) = 128 B = one cache line = 32 words; word p (4 B) holds the
// half pair ( v_p[i0] , v_p[i0+1] ) where v_p = hop m=p (p<16) else ovl m=p-16.
// One LDG.128 per 8-lane group member fetches 4 m-values with BOTH grid rows.
// Size: 10 * 512 * 128 B = 640 KB (entry g=511 is built but never read).
__device__ __align__(128) __half g_tab[NB * NGRID * 64];

#define NTRANS  (NB * NM * NGRID)     // 81920 elements per source table
#define EPT     4                     // edges per thread
#define NG      (E_EDGES / EPT)       // 500,000 edge groups
#define ETHREADS (NG * 8)             // 4,000,000 edge threads

// ---------------------------------------------------------------------------
// Kernel 1: nodes + pair-interleaved table build, one launch (node half hides
// the transpose's scattered-store latency).
// Table build: value at (b, m, g) goes to entry (b,g) word m lo-half, and to
// entry (b,g-1) word m hi-half. Ovl uses word 16+m.
// ---------------------------------------------------------------------------
__global__ void __launch_bounds__(256)
prep_kernel(const float* __restrict__ hop,
            const float* __restrict__ ovl,
            const int*   __restrict__ atom_type,
            const float* __restrict__ onsiteE,
            float*       __restrict__ out) {
    int tid = blockIdx.x * blockDim.x + threadIdx.x;
    if (tid < N_NODES) {
        int at = __ldg(atom_type + tid);
        float4 v = __ldg((const float4*)onsiteE + at);
        __stcs(((float4*)(out + OUT_NODE_OFF)) + tid, v);
    } else {
        int idx = tid - N_NODES;
        if (idx >= NTRANS) return;
        int g = idx & (NGRID - 1);
        int m = (idx >> 9) & (NM - 1);
        int b = idx / (NGRID * NM);
        __half hv = __float2half(__ldg(hop + idx));
        __half ov = __float2half(__ldg(ovl + idx));
        // entry (b,g): 64 halfs. word p -> half index p*2 (+1 for hi).
        int ebase = ((b << 9) + g) << 6;
        g_tab[ebase + (m << 1)]             = hv;   // lo of word m
        g_tab[ebase + ((NM + m) << 1)]      = ov;   // lo of word 16+m
        if (g > 0) {
            int pbase = ((b << 9) + (g - 1)) << 6;
            g_tab[pbase + (m << 1) + 1]        = hv; // hi of word m
            g_tab[pbase + ((NM + m) << 1) + 1] = ov; // hi of word 16+m
        }
    }
}

// ---------------------------------------------------------------------------
// Kernel 2: edges only. 8 lanes/edge, EPT=4 edges/thread.
// Thread t: group gp = t>>3, slot s = t&7; edges e_k = gp + k*NG.
// Per edge: ONE LDG.128 at entry(b,i0) word range [4s, 4s+4).
//   word = (v[i0] lo, v[i0+1] hi) -> res = lo*w0 + hi*frac.
// Store: one contiguous float4 per (edge, slot): s<4 -> hop quad s,
// s>=4 -> ovl quad s-4. All 4 gathers in flight before any consume.
// ---------------------------------------------------------------------------
__global__ void __launch_bounds__(256)
edge_kernel(const float* __restrict__ rij,
            const int*   __restrict__ edge_type,
            float*       __restrict__ out) {
    int t = blockIdx.x * blockDim.x + threadIdx.x;
    if (t >= ETHREADS) return;
    int gp = t >> 3;
    int s  = t & 7;
    const float DXf = (float)((10.0 - 1.0) / (double)(NGRID - 1));
    const uint4* tab4 = (const uint4*)g_tab;   // 8 uint4 per 128B entry

    float rv[EPT];
    int   bt[EPT];
    #pragma unroll
    for (int k = 0; k < EPT; k++) {
        rv[k] = __ldg(rij + gp + k * NG);
        bt[k] = __ldg(edge_type + gp + k * NG);
    }

    float frac[EPT], w0[EPT];
    int row[EPT];
    #pragma unroll
    for (int k = 0; k < EPT; k++) {
        float tt = (rv[k] - 1.0f) / DXf;
        int i0 = min(max((int)floorf(tt), 0), NGRID - 2);
        frac[k] = tt - (float)i0;
        w0[k] = 1.0f - frac[k];
        row[k] = (((bt[k] << 9) + i0) << 3) + s;   // uint4 index
    }

    uint4 d[EPT];
    #pragma unroll
    for (int k = 0; k < EPT; k++)
        d[k] = __ldg(tab4 + row[k]);

    int is_ovl = s >> 2;
    int q = s & 3;
    float4* outv = (float4*)out;
    #pragma unroll
    for (int k = 0; k < EPT; k++) {
        float2 p0 = __half22float2(*reinterpret_cast<const __half2*>(&d[k].x));
        float2 p1 = __half22float2(*reinterpret_cast<const __half2*>(&d[k].y));
        float2 p2 = __half22float2(*reinterpret_cast<const __half2*>(&d[k].z));
        float2 p3 = __half22float2(*reinterpret_cast<const __half2*>(&d[k].w));
        float4 res;
        res.x = p0.x * w0[k] + p0.y * frac[k];
        res.y = p1.x * w0[k] + p1.y * frac[k];
        res.z = p2.x * w0[k] + p2.y * frac[k];
        res.w = p3.x * w0[k] + p3.y * frac[k];
        int e = gp + k * NG;
        int dst4 = is_ovl * (OUT_OVL_OFF >> 2) + (e << 2) + q;
        __stcs(outv + dst4, res);
    }
}

// ---------------------------------------------------------------------------
// Launch
// ---------------------------------------------------------------------------
extern "C" void kernel_launch(void* const* d_in, const int* in_sizes, int n_in,
                              void* d_out, int out_size) {
    const float* rij       = (const float*)d_in[0];
    const int*   edge_type = (const int*)d_in[1];
    const int*   atom_type = (const int*)d_in[2];
    const float* hop       = (const float*)d_in[3];
    const float* ovl       = (const float*)d_in[4];
    const float* onsiteE   = (const float*)d_in[5];
    float* out = (float*)d_out;

    // 1) nodes + pair-interleaved table build
    {
        int total = N_NODES + NTRANS;               // 581,920
        int blk = 256;
        prep_kernel<<<(total + blk - 1) / blk, blk>>>(hop, ovl, atom_type,
                                                      onsiteE, out);
    }
    // 2) edges
    {
        int blk = 256;
        edge_kernel<<<(ETHREADS + blk - 1) / blk, blk>>>(rij, edge_type, out);
    }
}

// round 9
// speedup vs baseline: 1.0336x; 1.0336x over previous
#include <cuda_runtime.h>
#include <cuda_fp16.h>

// Problem constants (match reference)
#define NGRID 512
#define NB    10      // bond types
#define NM    16      // integrals
#define E_EDGES 2000000
#define N_NODES 500000

// Derived output offsets (floats)
#define OUT_OVL_OFF  (E_EDGES * NM)          // 32,000,000
#define OUT_NODE_OFF (2 * E_EDGES * NM)      // 64,000,000

// Grid-pair-interleaved fp16 table.
// Entry (b, i0) = 128 B = one cache line = 32 words; word p (4 B) holds the
// half pair ( v_p[i0] , v_p[i0+1] ) where v_p = hop m=p (p<16) else ovl m=p-16.
// One LDG.128 per 8-lane group member fetches 4 m-values with BOTH grid rows.
// Size: 10 * 512 * 128 B = 640 KB (entry g=511 built defensively, never read).
__device__ __align__(128) __half g_tab[NB * NGRID * 64];

#define NTRANS  (NB * NM * NGRID)     // 81920 elements per source table
#define EPT     4                     // edges per thread
#define NG      (E_EDGES / EPT)       // 500,000 edge groups
#define ETHREADS (NG * 8)             // 4,000,000 edge threads

// 1/DX as compile-time fp32 constant (DX = 9/511)
#define INV_DX  ((float)((double)(NGRID - 1) / (10.0 - 1.0)))

// ---------------------------------------------------------------------------
// Kernel 1: pair-interleaved table build ONLY (tiny; nodes moved to kernel 2).
// Value at (b, m, g) -> entry (b,g) word m lo-half, entry (b,g-1) word m
// hi-half; ovl uses word 16+m.
// ---------------------------------------------------------------------------
__global__ void __launch_bounds__(256)
prep_kernel(const float* __restrict__ hop,
            const float* __restrict__ ovl) {
    int idx = blockIdx.x * blockDim.x + threadIdx.x;
    if (idx >= NTRANS) return;
    int g = idx & (NGRID - 1);
    int m = (idx >> 9) & (NM - 1);
    int b = idx / (NGRID * NM);
    __half hv = __float2half(__ldg(hop + idx));
    __half ov = __float2half(__ldg(ovl + idx));
    int ebase = ((b << 9) + g) << 6;            // 64 halfs per entry
    g_tab[ebase + (m << 1)]        = hv;        // lo of word m
    g_tab[ebase + ((NM + m) << 1)] = ov;        // lo of word 16+m
    if (g > 0) {
        int pbase = ((b << 9) + (g - 1)) << 6;
        g_tab[pbase + (m << 1) + 1]        = hv; // hi of word m
        g_tab[pbase + ((NM + m) << 1) + 1] = ov; // hi of word 16+m
    }
}

// ---------------------------------------------------------------------------
// Kernel 2: edges (8 lanes/edge, EPT=4 edges/thread) + nodes tail.
// Thread t: group gp = t>>3, slot s = t&7; edges e_k = gp + k*NG.
// Per edge: ONE LDG.128 at entry(b,i0), words [4s, 4s+4).
//   word = (v[i0], v[i0+1]) halfs -> res = lo*w0 + hi*frac   (fp32 math)
// All 4 gathers in flight before any consume. One contiguous float4 store
// per (edge, slot). Scalar prologue uses mul-by-invDX + truncation cast
// (tt >= 0 since rij >= X0) instead of divide + floorf.
// ---------------------------------------------------------------------------
__global__ void __launch_bounds__(256)
main_kernel(const float* __restrict__ rij,
            const int*   __restrict__ edge_type,
            const int*   __restrict__ atom_type,
            const float* __restrict__ onsiteE,
            float*       __restrict__ out) {
    int t = blockIdx.x * blockDim.x + threadIdx.x;

    if (t < ETHREADS) {
        int gp = t >> 3;
        int s  = t & 7;
        const uint4* tab4 = (const uint4*)g_tab;   // 8 uint4 per 128B entry

        float rv[EPT];
        int   bt[EPT];
        #pragma unroll
        for (int k = 0; k < EPT; k++) {
            rv[k] = __ldg(rij + gp + k * NG);
            bt[k] = __ldg(edge_type + gp + k * NG);
        }

        float frac[EPT], w0[EPT];
        int row[EPT];
        #pragma unroll
        for (int k = 0; k < EPT; k++) {
            float tt = (rv[k] - 1.0f) * INV_DX;    // tt >= 0 by input domain
            int i0 = min((int)tt, NGRID - 2);
            frac[k] = tt - (float)i0;
            w0[k] = 1.0f - frac[k];
            row[k] = (((bt[k] << 9) + i0) << 3) + s;   // uint4 index
        }

        uint4 d[EPT];
        #pragma unroll
        for (int k = 0; k < EPT; k++)
            d[k] = __ldg(tab4 + row[k]);

        int is_ovl = s >> 2;
        int q = s & 3;
        float4* outv = (float4*)out;
        #pragma unroll
        for (int k = 0; k < EPT; k++) {
            float2 p0 = __half22float2(*reinterpret_cast<const __half2*>(&d[k].x));
            float2 p1 = __half22float2(*reinterpret_cast<const __half2*>(&d[k].y));
            float2 p2 = __half22float2(*reinterpret_cast<const __half2*>(&d[k].z));
            float2 p3 = __half22float2(*reinterpret_cast<const __half2*>(&d[k].w));
            float4 res;
            res.x = p0.x * w0[k] + p0.y * frac[k];
            res.y = p1.x * w0[k] + p1.y * frac[k];
            res.z = p2.x * w0[k] + p2.y * frac[k];
            res.w = p3.x * w0[k] + p3.y * frac[k];
            int e = gp + k * NG;
            int dst4 = is_ovl * (OUT_OVL_OFF >> 2) + (e << 2) + q;
            __stcs(outv + dst4, res);
        }
    } else {
        int n = t - ETHREADS;
        if (n < N_NODES) {
            int at = __ldg(atom_type + n);
            float4 v = __ldg((const float4*)onsiteE + at);
            __stcs(((float4*)(out + OUT_NODE_OFF)) + n, v);
        }
    }
}

// ---------------------------------------------------------------------------
// Launch
// ---------------------------------------------------------------------------
extern "C" void kernel_launch(void* const* d_in, const int* in_sizes, int n_in,
                              void* d_out, int out_size) {
    const float* rij       = (const float*)d_in[0];
    const int*   edge_type = (const int*)d_in[1];
    const int*   atom_type = (const int*)d_in[2];
    const float* hop       = (const float*)d_in[3];
    const float* ovl       = (const float*)d_in[4];
    const float* onsiteE   = (const float*)d_in[5];
    float* out = (float*)d_out;

    // 1) pair-interleaved table build (tiny)
    {
        int blk = 256;
        prep_kernel<<<(NTRANS + blk - 1) / blk, blk>>>(hop, ovl);
    }
    // 2) edges + nodes
    {
        int total = ETHREADS + N_NODES;             // 4,500,000
        int blk = 256;
        main_kernel<<<(total + blk - 1) / blk, blk>>>(rij, edge_type,
                                                      atom_type, onsiteE, out);
    }
}